// round 2
// baseline (speedup 1.0000x reference)
#include <cuda_runtime.h>
#include <cstdint>

#define MAXN 100000
#define D 64
#define UP 204            // padded U row stride (floats), 16B-aligned, bank-skewed
#define TILE_N 64

// Scratch: [2][N][64] float accumulators (sum of x[src] per (half, dst)) + counts
__device__ float g_acc[2UL * MAXN * D];
__device__ int   g_cnt[2 * MAXN];

// ---------------------------------------------------------------------------
__global__ void zero_kernel(int n) {
    int tid = blockIdx.x * blockDim.x + threadIdx.x;
    int nt  = gridDim.x * blockDim.x;
    int total4 = 2 * n * (D / 4);
    float4 z = make_float4(0.f, 0.f, 0.f, 0.f);
    float4* a4 = reinterpret_cast<float4*>(g_acc);
    for (int i = tid; i < total4; i += nt) a4[i] = z;
    for (int i = tid; i < 2 * n; i += nt) g_cnt[i] = 0;
}

// ---------------------------------------------------------------------------
// One work item per (edge, float4-chunk): 16 threads cooperate per edge.
// Scatter x[src[e]] into g_acc[half][dst[e]] with vector f32 reductions.
__global__ void scatter_kernel(const float* __restrict__ x,
                               const int* __restrict__ src,
                               const int* __restrict__ dst,
                               int E, int half, int n) {
    long gid = (long)blockIdx.x * blockDim.x + threadIdx.x;
    if (gid >= (long)E * 16) return;
    int e = (int)(gid >> 4);
    int j = (int)(gid & 15);
    int s = __ldg(src + e);
    int d = __ldg(dst + e);
    int hsel = (e >= half) ? 1 : 0;

    float4 v = __ldg(reinterpret_cast<const float4*>(x + (size_t)s * D) + j);
    float* p = g_acc + ((size_t)hsel * n + d) * D + j * 4;
    asm volatile("red.global.add.v4.f32 [%0], {%1,%2,%3,%4};"
                 :: "l"(p), "f"(v.x), "f"(v.y), "f"(v.z), "f"(v.w)
                 : "memory");
    if (j == 0) atomicAdd(&g_cnt[hsel * n + d], 1);
}

// ---------------------------------------------------------------------------
// Node kernel: out[n] = U[n] @ Wcat^T + K + cO*bO + cI*bI
//   U[n]    = [ x[n] | A_O[n] - cO*x[n] | A_I[n] - cI*x[n] ]   (192 wide)
//   Wcat    = [ W_S ; W_O ; W_I ]                              (64 x 192)
//   K[d]    = b_S[d] - r . W_S[d]
// Block: 256 threads, tile of 64 nodes, each thread a 4x4 micro-tile.
__global__ void node_kernel(const float* __restrict__ x,
                            const float* __restrict__ r,
                            const float* __restrict__ W_O, const float* __restrict__ b_O,
                            const float* __restrict__ W_I, const float* __restrict__ b_I,
                            const float* __restrict__ W_S, const float* __restrict__ b_S,
                            float* __restrict__ out, int n) {
    extern __shared__ float sm[];
    float* WT  = sm;                    // [192][64]  WT[k][d] = Wcat[d][k]
    float* U   = WT + 192 * 64;         // [64][UP]
    float* Ksm = U + 64 * UP;           // [64]
    float* bOs = Ksm + 64;              // [64]
    float* bIs = bOs + 64;              // [64]
    float* cOs = bIs + 64;              // [64]
    float* cIs = cOs + 64;              // [64]

    int tid = threadIdx.x;
    int node0 = blockIdx.x * TILE_N;

    // ---- stage transposed weights: seg0=W_S, seg1=W_O, seg2=W_I ----
    {
        int dd = tid & 63;
        int q0 = tid >> 6;  // 0..3
        const float* Ws[3] = { W_S, W_O, W_I };
        #pragma unroll
        for (int m = 0; m < 3; m++) {
            const float* W = Ws[m];
            for (int q = q0; q < 16; q += 4) {
                float4 w = __ldg(reinterpret_cast<const float4*>(W + dd * 64) + q);
                int kb = m * 64 + q * 4;
                WT[(kb + 0) * 64 + dd] = w.x;
                WT[(kb + 1) * 64 + dd] = w.y;
                WT[(kb + 2) * 64 + dd] = w.z;
                WT[(kb + 3) * 64 + dd] = w.w;
            }
        }
    }

    // ---- constants, biases, counts ----
    if (tid < 64) {
        float acc = b_S[tid];
        const float* wrow = W_S + tid * 64;
        #pragma unroll 8
        for (int k = 0; k < 64; k++) acc -= r[k] * wrow[k];
        Ksm[tid] = acc;
        bOs[tid] = b_O[tid];
        bIs[tid] = b_I[tid];
        int nn = node0 + tid;
        cOs[tid] = (nn < n) ? (float)g_cnt[nn] : 0.f;
        cIs[tid] = (nn < n) ? (float)g_cnt[n + nn] : 0.f;
    }

    // ---- stage raw U = [x | A_O | A_I] ----
    {
        int kq  = tid & 15;   // float4 index within 64
        int nl0 = tid >> 4;   // 0..15
        for (int nl = nl0; nl < TILE_N; nl += 16) {
            int nn = node0 + nl;
            float4 vx = make_float4(0, 0, 0, 0), vo = vx, vi = vx;
            if (nn < n) {
                vx = __ldg(reinterpret_cast<const float4*>(x + (size_t)nn * D) + kq);
                vo = *(reinterpret_cast<const float4*>(g_acc + (size_t)nn * D) + kq);
                vi = *(reinterpret_cast<const float4*>(g_acc + ((size_t)n + nn) * D) + kq);
            }
            float4* Ur = reinterpret_cast<float4*>(U + nl * UP);
            Ur[kq]      = vx;
            Ur[16 + kq] = vo;
            Ur[32 + kq] = vi;
        }
    }
    __syncthreads();

    // ---- fixup: subtract count * x ----
    {
        int kq  = tid & 15;
        int nl0 = tid >> 4;
        for (int nl = nl0; nl < TILE_N; nl += 16) {
            float cO = cOs[nl], cI = cIs[nl];
            float4* Ur = reinterpret_cast<float4*>(U + nl * UP);
            float4 vx = Ur[kq];
            float4 vo = Ur[16 + kq];
            float4 vi = Ur[32 + kq];
            vo.x -= cO * vx.x; vo.y -= cO * vx.y; vo.z -= cO * vx.z; vo.w -= cO * vx.w;
            vi.x -= cI * vx.x; vi.y -= cI * vx.y; vi.z -= cI * vx.z; vi.w -= cI * vx.w;
            Ur[16 + kq] = vo;
            Ur[32 + kq] = vi;
        }
    }
    __syncthreads();

    // ---- main GEMM: 4 nodes x 4 outputs per thread ----
    int tx = tid & 15;       // output quad
    int ty = tid >> 4;       // node quad
    const float* Brow = WT + tx * 4;
    const float* U0 = U + (ty * 4 + 0) * UP;
    const float* U1 = U0 + UP;
    const float* U2 = U1 + UP;
    const float* U3 = U2 + UP;

    float acc[4][4];
    #pragma unroll
    for (int i = 0; i < 4; i++)
        #pragma unroll
        for (int j = 0; j < 4; j++) acc[i][j] = 0.f;

    #pragma unroll 4
    for (int k = 0; k < 192; k++) {
        float4 b = *reinterpret_cast<const float4*>(Brow + k * 64);
        float a0 = U0[k], a1 = U1[k], a2 = U2[k], a3 = U3[k];
        acc[0][0] += a0 * b.x; acc[0][1] += a0 * b.y; acc[0][2] += a0 * b.z; acc[0][3] += a0 * b.w;
        acc[1][0] += a1 * b.x; acc[1][1] += a1 * b.y; acc[1][2] += a1 * b.z; acc[1][3] += a1 * b.w;
        acc[2][0] += a2 * b.x; acc[2][1] += a2 * b.y; acc[2][2] += a2 * b.z; acc[2][3] += a2 * b.w;
        acc[3][0] += a3 * b.x; acc[3][1] += a3 * b.y; acc[3][2] += a3 * b.z; acc[3][3] += a3 * b.w;
    }

    // ---- epilogue ----
    float k0 = Ksm[tx * 4 + 0], k1 = Ksm[tx * 4 + 1], k2 = Ksm[tx * 4 + 2], k3 = Ksm[tx * 4 + 3];
    float bo0 = bOs[tx * 4 + 0], bo1 = bOs[tx * 4 + 1], bo2 = bOs[tx * 4 + 2], bo3 = bOs[tx * 4 + 3];
    float bi0 = bIs[tx * 4 + 0], bi1 = bIs[tx * 4 + 1], bi2 = bIs[tx * 4 + 2], bi3 = bIs[tx * 4 + 3];
    #pragma unroll
    for (int i = 0; i < 4; i++) {
        int nl = ty * 4 + i;
        int nn = node0 + nl;
        if (nn >= n) continue;
        float cO = cOs[nl], cI = cIs[nl];
        float4 o;
        o.x = acc[i][0] + k0 + cO * bo0 + cI * bi0;
        o.y = acc[i][1] + k1 + cO * bo1 + cI * bi1;
        o.z = acc[i][2] + k2 + cO * bo2 + cI * bi2;
        o.w = acc[i][3] + k3 + cO * bo3 + cI * bi3;
        *(reinterpret_cast<float4*>(out + (size_t)nn * D) + tx) = o;
    }
}

// ---------------------------------------------------------------------------
__global__ void rout_kernel(const float* __restrict__ r,
                            const float* __restrict__ W_R,
                            const float* __restrict__ b_R,
                            float* __restrict__ out, int n) {
    int d = threadIdx.x;
    if (d >= D) return;
    float acc = b_R[d];
    const float* wrow = W_R + d * 64;
    #pragma unroll 8
    for (int k = 0; k < 64; k++) acc += r[k] * wrow[k];
    out[(size_t)n * D + d] = acc;
}

// ---------------------------------------------------------------------------
extern "C" void kernel_launch(void* const* d_in, const int* in_sizes, int n_in,
                              void* d_out, int out_size) {
    const float* x   = (const float*)d_in[0];
    const float* r   = (const float*)d_in[1];
    const int*   src = (const int*)d_in[2];
    const int*   dst = (const int*)d_in[3];
    const float* W_O = (const float*)d_in[4];
    const float* b_O = (const float*)d_in[5];
    const float* W_I = (const float*)d_in[6];
    const float* b_I = (const float*)d_in[7];
    const float* W_S = (const float*)d_in[8];
    const float* b_S = (const float*)d_in[9];
    const float* W_R = (const float*)d_in[10];
    const float* b_R = (const float*)d_in[11];
    float* out = (float*)d_out;

    int n = in_sizes[0] / D;       // 100000
    int E = in_sizes[2];           // 1200000
    int half = E / 2;

    const int SMEM_BYTES = (192 * 64 + 64 * UP + 5 * 64) * sizeof(float);
    cudaFuncSetAttribute(node_kernel, cudaFuncAttributeMaxDynamicSharedMemorySize, SMEM_BYTES);

    zero_kernel<<<2048, 256>>>(n);

    long items = (long)E * 16;
    int sblocks = (int)((items + 255) / 256);
    scatter_kernel<<<sblocks, 256>>>(x, src, dst, E, half, n);

    int nblocks = (n + TILE_N - 1) / TILE_N;
    node_kernel<<<nblocks, 256, SMEM_BYTES>>>(x, r, W_O, b_O, W_I, b_I, W_S, b_S, out, n);

    rout_kernel<<<1, 64>>>(r, W_R, b_R, out, n);
}